// round 8
// baseline (speedup 1.0000x reference)
#include <cuda_runtime.h>
#include <cuda_fp16.h>
#include <stdint.h>

#define NN 4096
#define FC 256      // F_IN == F_OUT
#define BB 8
#define WORDS (NN / 32)

// ---------------- scratch (no allocations allowed) ----------------
__device__ uint32_t g_adj[NN * WORDS];            // 2 MB bitmask adjacency
__device__ __half   g_xt[(size_t)BB * NN * FC];   // 16 MB: xt = x @ W (fp16)
__device__ __half   g_wh[FC * FC];                // 128 KB: W^T as fp16 [n][k]

// =================== setup kernels ===================
__global__ void k_clear_adj() {
    int i = blockIdx.x * blockDim.x + threadIdx.x;
    if (i < NN * WORDS) g_adj[i] = 0u;
}
__global__ void k_scatter(const int* __restrict__ ei, int E) {
    int e = blockIdx.x * blockDim.x + threadIdx.x;
    if (e < E) {
        int src = ei[e];
        int dst = ei[E + e];
        atomicOr(&g_adj[src * WORDS + (dst >> 5)], 1u << (dst & 31));
    }
}
// W[k][n] -> g_wh[n][k] fp16 (tiled transpose, coalesced)
__global__ void k_wt(const float* __restrict__ W) {
    __shared__ float tile[32][33];
    const int bn = blockIdx.x * 32;
    const int bk = blockIdx.y * 32;
    const int tx = threadIdx.x, ty = threadIdx.y;
#pragma unroll
    for (int r = ty; r < 32; r += 8)
        tile[r][tx] = W[(size_t)(bk + r) * FC + bn + tx];
    __syncthreads();
#pragma unroll
    for (int r = ty; r < 32; r += 8)
        g_wh[(size_t)(bn + r) * FC + bk + tx] = __float2half_rn(tile[tx][r]);
}

// =================== mma / cp.async / ldmatrix helpers ===================
__device__ __forceinline__ void mma_f16(float* d, const uint32_t* a, const uint32_t* b) {
    asm volatile(
        "mma.sync.aligned.m16n8k16.row.col.f32.f16.f16.f32 "
        "{%0,%1,%2,%3}, {%4,%5,%6,%7}, {%8,%9}, {%0,%1,%2,%3};"
        : "+f"(d[0]), "+f"(d[1]), "+f"(d[2]), "+f"(d[3])
        : "r"(a[0]), "r"(a[1]), "r"(a[2]), "r"(a[3]),
          "r"(b[0]), "r"(b[1]));
}
__device__ __forceinline__ uint32_t smem_u32(const void* p) {
    uint32_t a;
    asm("{ .reg .u64 t; cvta.to.shared.u64 t, %1; cvt.u32.u64 %0, t; }" : "=r"(a) : "l"(p));
    return a;
}
#define LDSM_X4(r0, r1, r2, r3, addr)                                        \
    asm volatile("ldmatrix.sync.aligned.m8n8.x4.shared.b16 {%0,%1,%2,%3}, [%4];" \
        : "=r"(r0), "=r"(r1), "=r"(r2), "=r"(r3) : "r"(addr))
#define CP_ASYNC16(dst, src) \
    asm volatile("cp.async.cg.shared.global [%0], [%1], 16;" :: "r"(dst), "l"(src))
#define CP_COMMIT() asm volatile("cp.async.commit_group;" ::: "memory")
#define CP_WAIT0()  asm volatile("cp.async.wait_group 0;" ::: "memory")
#define CP_WAIT1()  asm volatile("cp.async.wait_group 1;" ::: "memory")

// =================== kernel: xt = x @ W  (fused fp32->fp16 + mma) ===================
// Tiles 128x128, BK=64. A staged as raw fp32 (cp.async), converted per-chunk
// into one swizzled fp16 buffer feeding the R7 ldmatrix path. B fp16 staged.
#define BM 128
#define BN 128
#define BK 64
#define NCH (FC / BK)            // 4
#define A32_OFF(p) ((p) * 32768)             // 2 x 32 KB fp32 A stages
#define B16_OFF(p) (65536 + (p) * 16384)     // 2 x 16 KB fp16 B stages
#define A16_OFF    (98304)                   // 16 KB fp16 A convert buffer
#define GEMM_SMEM  (114688)                  // 112 KB

__global__ __launch_bounds__(256) void k_gemm(const float* __restrict__ X) {
    extern __shared__ char sm[];
    const uint32_t sb = smem_u32(sm);

    const int tid  = threadIdx.x;
    const int lane = tid & 31;
    const int wid  = tid >> 5;
    const int wm = (wid & 1) * 64;
    const int wn = (wid >> 1) * 32;
    const int bm = blockIdx.x * BM;
    const int bn = blockIdx.y * BN;
    const int g  = lane >> 2;
    const int tg = lane & 3;

    // ldmatrix per-lane terms
    const int a_lrow  = lane & 15;
    const int a_lchnk = lane >> 4;
    const int b_lrow  = ((lane >> 4) << 3) + (lane & 7);
    const int b_lchnk = (lane >> 3) & 1;

    float acc[4][4][4];
#pragma unroll
    for (int mt = 0; mt < 4; mt++)
#pragma unroll
        for (int nt = 0; nt < 4; nt++)
#pragma unroll
            for (int r = 0; r < 4; r++) acc[mt][nt][r] = 0.0f;

    auto issue = [&](int c, int p) {
        const int k0 = c * BK;
#pragma unroll
        for (int q = 0; q < 8; q++) {         // A fp32: 128 rows x 64 floats
            int id  = q * 256 + tid;
            int row = id >> 4;
            int ch  = id & 15;
            uint32_t dst = sb + A32_OFF(p) + row * 256
                         + ((ch ^ ((row & 7) << 1)) << 4);
            CP_ASYNC16(dst, &X[(size_t)(bm + row) * FC + k0 + ch * 4]);
        }
#pragma unroll
        for (int q = 0; q < 4; q++) {         // B fp16: 128 rows x 64 halves
            int id  = q * 256 + tid;
            int row = id >> 3;
            int ch  = id & 7;
            uint32_t dst = sb + B16_OFF(p) + row * 128 + ((ch ^ (row & 7)) << 4);
            CP_ASYNC16(dst, &g_wh[(size_t)(bn + row) * FC + k0 + ch * 8]);
        }
        CP_COMMIT();
    };

    issue(0, 0);
    issue(1, 1);

    const int cv_r = tid >> 1;      // convert-stage row (2 threads/row)
    const int cv_h = tid & 1;       // row half

#pragma unroll
    for (int c = 0; c < NCH; c++) {
        const int p = c & 1;
        if (c == NCH - 1) { CP_WAIT0(); } else { CP_WAIT1(); }
        __syncthreads();

        // ---- convert stage: A32[p] -> A16 (swizzled fp16) ----
        {
            const char* src = sm + A32_OFF(p) + cv_r * 256;
            char* dstb = sm + A16_OFF + cv_r * 128;
            const int rx2 = (cv_r & 7) << 1;
            const int rx  = cv_r & 7;
#pragma unroll
            for (int jj = 0; jj < 4; jj++) {
                int c0 = (cv_h * 8 + 2 * jj)     ^ rx2;
                int c1 = (cv_h * 8 + 2 * jj + 1) ^ rx2;
                float4 f0 = *(const float4*)(src + c0 * 16);
                float4 f1 = *(const float4*)(src + c1 * 16);
                __half2 h0 = __floats2half2_rn(f0.x, f0.y);
                __half2 h1 = __floats2half2_rn(f0.z, f0.w);
                __half2 h2 = __floats2half2_rn(f1.x, f1.y);
                __half2 h3 = __floats2half2_rn(f1.z, f1.w);
                int cc = (cv_h * 4 + jj) ^ rx;
                *(uint4*)(dstb + cc * 16) = make_uint4(
                    *(uint32_t*)&h0, *(uint32_t*)&h1,
                    *(uint32_t*)&h2, *(uint32_t*)&h3);
            }
        }
        __syncthreads();

        // ---- mma stage (identical to R7, A from A16 buffer) ----
        const uint32_t sA = sb + A16_OFF;
        const uint32_t sB = sb + B16_OFF(p);
#pragma unroll
        for (int s = 0; s < 4; s++) {
            uint32_t a[4][4], b[4][2];
#pragma unroll
            for (int mt = 0; mt < 4; mt++) {
                int row = wm + mt * 16 + a_lrow;
                int ch  = (s * 2 + a_lchnk) ^ (row & 7);
                LDSM_X4(a[mt][0], a[mt][1], a[mt][2], a[mt][3],
                        sA + row * 128 + (ch << 4));
            }
#pragma unroll
            for (int pr = 0; pr < 2; pr++) {
                int row = wn + pr * 16 + b_lrow;
                int ch  = (s * 2 + b_lchnk) ^ (row & 7);
                LDSM_X4(b[pr * 2][0], b[pr * 2][1], b[pr * 2 + 1][0], b[pr * 2 + 1][1],
                        sB + row * 128 + (ch << 4));
            }
#pragma unroll
            for (int mt = 0; mt < 4; mt++)
#pragma unroll
                for (int nt = 0; nt < 4; nt++)
                    mma_f16(acc[mt][nt], a[mt], b[nt]);
        }
        __syncthreads();
        if (c + 2 < NCH) issue(c + 2, p);
    }

    // ---- epilogue: fp32 acc -> fp16 g_xt ----
#pragma unroll
    for (int mt = 0; mt < 4; mt++) {
#pragma unroll
        for (int nt = 0; nt < 4; nt++) {
            int r = bm + wm + mt * 16 + g;
            int c = bn + wn + nt * 8 + tg * 2;
            __half2 h01 = __floats2half2_rn(acc[mt][nt][0], acc[mt][nt][1]);
            __half2 h23 = __floats2half2_rn(acc[mt][nt][2], acc[mt][nt][3]);
            *(__half2*)&g_xt[(size_t)r * FC + c]       = h01;
            *(__half2*)&g_xt[(size_t)(r + 8) * FC + c] = h23;
        }
    }
}

// =================== kernel: aggregate ===================
// thread t: batch b = t>>5, features f8 = (t&31)*8 (one LDG.128 / neighbor)
__global__ __launch_bounds__(256) void k_aggregate(const float* __restrict__ bias,
                                                   float* __restrict__ out) {
    __shared__ int s_nbr[NN];
    __shared__ int s_off[WORDS];
    __shared__ int s_total;

    const int i = blockIdx.x;
    const int t = threadIdx.x;
    const int b  = t >> 5;
    const int f8 = (t & 31) * 8;

    uint32_t word = (t < WORDS) ? g_adj[i * WORDS + t] : 0u;
    if (t < WORDS) s_off[t] = __popc(word);
    __syncthreads();

    if (t < 32) {   // warp 0: exclusive scan of 128 popcounts
        int v0 = s_off[4 * t], v1 = s_off[4 * t + 1];
        int v2 = s_off[4 * t + 2], v3 = s_off[4 * t + 3];
        int sum = v0 + v1 + v2 + v3;
        int inc = sum;
#pragma unroll
        for (int d = 1; d < 32; d <<= 1) {
            int x = __shfl_up_sync(0xFFFFFFFFu, inc, d);
            if (t >= d) inc += x;
        }
        int exc = inc - sum;
        s_off[4 * t] = exc;
        s_off[4 * t + 1] = exc + v0;
        s_off[4 * t + 2] = exc + v0 + v1;
        s_off[4 * t + 3] = exc + v0 + v1 + v2;
        if (t == 31) s_total = inc;
    }
    __syncthreads();

    if (t < WORDS) {
        int pos = s_off[t];
        uint32_t m = word;
        while (m) {
            int bit = __ffs(m) - 1;
            m &= m - 1;
            s_nbr[pos++] = t * 32 + bit;
        }
    }
    __syncthreads();

    const int n = s_total;
    const float inv = 1.0f / ((float)n + 1e-6f);
    const __half* __restrict__ xb = g_xt + (size_t)b * NN * FC + f8;

    float a0 = 0.f, a1 = 0.f, a2 = 0.f, a3 = 0.f;
    float a4 = 0.f, a5 = 0.f, a6 = 0.f, a7 = 0.f;

#define ACC8(v)                                               \
    do { const __half2* _h = (const __half2*)&(v); float2 _p; \
        _p = __half22float2(_h[0]); a0 += _p.x; a1 += _p.y;   \
        _p = __half22float2(_h[1]); a2 += _p.x; a3 += _p.y;   \
        _p = __half22float2(_h[2]); a4 += _p.x; a5 += _p.y;   \
        _p = __half22float2(_h[3]); a6 += _p.x; a7 += _p.y; } while (0)

    int k = 0;
    for (; k + 4 <= n; k += 4) {
        uint4 v0 = *(const uint4*)&xb[(size_t)s_nbr[k]     * FC];
        uint4 v1 = *(const uint4*)&xb[(size_t)s_nbr[k + 1] * FC];
        uint4 v2 = *(const uint4*)&xb[(size_t)s_nbr[k + 2] * FC];
        uint4 v3 = *(const uint4*)&xb[(size_t)s_nbr[k + 3] * FC];
        ACC8(v0); ACC8(v1); ACC8(v2); ACC8(v3);
    }
    for (; k < n; k++) {
        uint4 v0 = *(const uint4*)&xb[(size_t)s_nbr[k] * FC];
        ACC8(v0);
    }
#undef ACC8

    float4 bl = *(const float4*)&bias[f8];
    float4 bh = *(const float4*)&bias[f8 + 4];
    float* o = out + ((size_t)b * NN + i) * FC + f8;
    *(float4*)o       = make_float4(a0 * inv + bl.x, a1 * inv + bl.y,
                                    a2 * inv + bl.z, a3 * inv + bl.w);
    *(float4*)(o + 4) = make_float4(a4 * inv + bh.x, a5 * inv + bh.y,
                                    a6 * inv + bh.z, a7 * inv + bh.w);
}

// =================== launch ===================
extern "C" void kernel_launch(void* const* d_in, const int* in_sizes, int n_in,
                              void* d_out, int out_size) {
    const float* x    = (const float*)d_in[0];
    const int*   ei   = (const int*)d_in[1];
    const float* w    = (const float*)d_in[2];
    const float* bias = (const float*)d_in[3];
    float*       out  = (float*)d_out;

    const int E = in_sizes[1] / 2;
    const int M = BB * NN;

    cudaFuncSetAttribute(k_gemm, cudaFuncAttributeMaxDynamicSharedMemorySize,
                         GEMM_SMEM);

    k_clear_adj<<<(NN * WORDS + 255) / 256, 256>>>();
    k_scatter<<<(E + 255) / 256, 256>>>(ei, E);
    {
        dim3 tb(32, 8);
        dim3 tg(FC / 32, FC / 32);
        k_wt<<<tg, tb>>>(w);
    }

    dim3 ggrid(M / BM, FC / BN);
    k_gemm<<<ggrid, 256, GEMM_SMEM>>>(x);

    k_aggregate<<<NN, 256>>>(bias, out);
}